// round 16
// baseline (speedup 1.0000x reference)
#include <cuda_runtime.h>
#include <cstdint>

#define B_ 128
#define I_ 64
#define S_ 2048
#define H_ 128
#define O_ 64
#define G4H 512
#define NC 32          // clusters
#define GH 8           // CTAs per cluster (h-slices, 16 h each)
#define BPC 4          // batches per cluster
#define THREADS 256

typedef unsigned long long ull;

// ---------------- device scratch (static) ----------------
__device__ float g_gx[(size_t)NC * S_ * GH * BPC * 64];  // [bi][t][hj][b][cl]
__device__ float g_hs[(size_t)B_ * S_ * H_];             // [b][t][h]

// ---------------- smem layout (float offsets) ----------------
#define OFF_W1 0
#define OFF_W2 8208
#define OFF_X1 24608
#define OFF_X2 25136
#define MBAR_F 26192               // 8 mbarriers x 8B = 16 floats
#define SMEM_FLOATS 26208
#define SMEM_BYTES (SMEM_FLOATS * 4)   // 104832 B -> 2 CTAs/SM

#define FMA2(d,a,b,c)  asm("fma.rn.f32x2 %0, %1, %2, %3;" : "=l"(d) : "l"(a), "l"(b), "l"(c))
#define PACK2(d,lo,hi) asm("mov.b64 %0, {%1, %2};" : "=l"(d) : "f"(lo), "f"(hi))
#define UNPACK2(lo,hi,s) asm("mov.b64 {%0, %1}, %2;" : "=f"(lo), "=f"(hi) : "l"(s))

__device__ __forceinline__ float tanhapx(float x) {
    float y; asm("tanh.approx.f32 %0, %1;" : "=f"(y) : "f"(x)); return y;
}
__device__ __forceinline__ uint32_t smem_u32(const void* p) {
    uint32_t a;
    asm("{ .reg .u64 t; cvta.to.shared.u64 t, %1; cvt.u32.u64 %0, t; }" : "=r"(a) : "l"(p));
    return a;
}
__device__ __forceinline__ uint32_t mapa_rank(uint32_t laddr, uint32_t rank) {
    uint32_t ra;
    asm("mapa.shared::cluster.u32 %0, %1, %2;" : "=r"(ra) : "r"(laddr), "r"(rank));
    return ra;
}
__device__ __forceinline__ void st_async_b32(uint32_t da, float v, uint32_t ma) {
    asm volatile("st.async.shared::cluster.mbarrier::complete_tx::bytes.b32 [%0], %1, [%2];"
                 :: "r"(da), "r"(__float_as_uint(v)), "r"(ma) : "memory");
}
#define MB_INIT(mb, n) asm volatile("mbarrier.init.shared.b64 [%0], %1;" :: "r"(mb), "r"((uint32_t)(n)) : "memory")
#define EXPECT_TX(mb, n) asm volatile("mbarrier.arrive.expect_tx.shared.b64 _, [%0], %1;" :: "r"(mb), "r"((uint32_t)(n)) : "memory")
__device__ __forceinline__ void waitp(uint32_t mb, uint32_t par) {
    uint32_t done;
    do {
        asm volatile("{\n\t.reg .pred p;\n\t"
            "mbarrier.try_wait.parity.acquire.cta.shared::cta.b64 p, [%1], %2, 0x989680;\n\t"
            "selp.b32 %0, 1, 0, p;\n\t}"
            : "=r"(done) : "r"(mb), "r"(par) : "memory");
    } while (!done);
}
__device__ __forceinline__ void cluster_sync() {
    asm volatile("barrier.cluster.arrive.aligned;\n\t"
                 "barrier.cluster.wait.aligned;" ::: "memory");
}

// ================= pre-pass: gx = x_t @ Wx_out + b_out =================
__global__ __launch_bounds__(256) void prepass(const float* __restrict__ x,
                                               const float* __restrict__ Wx_out,
                                               const float* __restrict__ b_out)
{
    __shared__ float sW[64 * 64];       // [i][cl]
    __shared__ float sx[4 * 64 * 16];   // [b][i][16t]
    const int tid = threadIdx.x;
    const int tc = blockIdx.x, hj = blockIdx.y, bi = blockIdx.z;
    const int cl = tid & 63, b = tid >> 6;
    const int gcl = (cl & 3) * H_ + hj * 16 + (cl >> 2);

    for (int idx = tid; idx < 64 * 64; idx += 256) {
        int i = idx >> 6, c2 = idx & 63;
        int gc2 = (c2 & 3) * H_ + hj * 16 + (c2 >> 2);
        sW[idx] = Wx_out[i * G4H + gc2];
    }
    const float bias = b_out[gcl];
    __syncthreads();

    for (int tile = 0; tile < 16; tile++) {
        int t0 = tc * 256 + tile * 16;
        for (int n = 0; n < 16; n++) {
            int flat = n * 256 + tid;
            int ttl = flat & 15, i = (flat >> 4) & 63, bb = flat >> 10;
            sx[(bb * 64 + i) * 16 + ttl] =
                x[((size_t)(bi * 4 + bb) * 64 + i) * S_ + t0 + ttl];
        }
        __syncthreads();

        ull acc[8];
#pragma unroll
        for (int tp = 0; tp < 8; tp++) PACK2(acc[tp], bias, bias);
#pragma unroll 8
        for (int i = 0; i < 64; i++) {
            float wv = sW[i * 64 + cl];
            ull wp; PACK2(wp, wv, wv);
            const ull* xp = (const ull*)(sx + (b * 64 + i) * 16);
#pragma unroll
            for (int tp = 0; tp < 8; tp++) FMA2(acc[tp], wp, xp[tp], acc[tp]);
        }
        float* outp = g_gx + (((size_t)bi * S_ + t0) * GH + hj) * 256 + b * 64 + cl;
#pragma unroll
        for (int tp = 0; tp < 8; tp++) {
            float lo, hi; UNPACK2(lo, hi, acc[tp]);
            outp[(size_t)(2 * tp) * 2048]     = lo;
            outp[(size_t)(2 * tp + 1) * 2048] = hi;
        }
        __syncthreads();
    }
}

// ================= main recurrent kernel =================
__global__ void __cluster_dims__(GH, 1, 1) __launch_bounds__(THREADS, 2)
nlstm_rec(const float* __restrict__ Wh_out,
          const float* __restrict__ Wx_in, const float* __restrict__ Wh_in,
          const float* __restrict__ b_in,
          const float* __restrict__ W_lin, const float* __restrict__ b_lin,
          float* __restrict__ out)
{
    extern __shared__ float sm[];
    const int tid = threadIdx.x;
    const int hj = blockIdx.x;          // 0..7
    const int bi = blockIdx.y;          // 0..31
    const int bg0 = bi * BPC;
    const int hg0 = hj * 16;
    const uint32_t sbase = smem_u32(sm);
    const uint32_t mbar0 = sbase + MBAR_F * 4;
    // barrier layout: [A0p0,A0p1, A1p0,A1p1, B0p0,B0p1, B1p0,B1p1] (8B each)

    // ---- load weight slices into padded SMEM ----
    for (int idx = tid; idx < 128 * 64; idx += THREADS) {
        int k = idx >> 6, c2 = idx & 63;
        int gc = (c2 & 3) * H_ + hg0 + (c2 >> 2);
        int k4 = k >> 2, e = k & 3, kqq = k4 >> 3, j = k4 & 7;
        sm[OFF_W1 + (kqq * 513 + j * 64 + c2) * 4 + e] = Wh_out[k * G4H + gc];
    }
    for (int idx = tid; idx < 256 * 64; idx += THREADS) {
        int k = idx >> 6, c2 = idx & 63;
        int gc = (c2 & 3) * H_ + hg0 + (c2 >> 2);
        int k4 = k >> 2, e = k & 3, kqq = k4 >> 4, j = k4 & 15;
        sm[OFF_W2 + (kqq * 1025 + j * 64 + c2) * 4 + e] =
            (k < H_) ? Wx_in[k * G4H + gc] : Wh_in[(k - H_) * G4H + gc];
    }
    for (int idx = tid; idx < 528 + 1056; idx += THREADS)
        sm[OFF_X1 + idx] = 0.0f;

    // ---- roles ----
    const int warp = tid >> 5, lane = tid & 31;
    const int cl = warp * 8 + (lane & 7);   // gate column 0..63 (= hl*4+g)
    const int kq = lane >> 3;               // k-quarter AND own batch (0..3)
    const int g  = cl & 3;
    const int hl = cl >> 2;
    const int gcol = g * H_ + hg0 + hl;

    const float b2 = b_in[gcol];
    const float actA = (g == 3) ? 1.f : 0.5f;
    const float actS = (g == 3) ? 1.f : 0.5f;
    const float actC = (g == 3) ? 0.f : 0.5f;

    // exchange data addresses (loop-invariant)
    const int kA = (g == 0) ? (hg0 + hl) : (H_ + hg0 + hl);
    const uint32_t aA = sbase + (uint32_t)(OFF_X2 + kA * 4 + (kA >> 5) * 4 + kq) * 4;
    const int kB = hg0 + hl;
    const uint32_t aB = sbase + (uint32_t)(OFF_X1 + kB * 4 + (kB >> 5) * 4 + kq) * 4;

    // matvec pointers
    const float4* w4a = (const float4*)(sm + OFF_W1) + kq * 513 + cl;
    const float4* w4b = (const float4*)(sm + OFF_W2) + kq * 1025 + cl;
    const ull* x1  = (const ull*)(sm + OFF_X1 + kq * 132);
    const ull* x2a = (const ull*)(sm + OFF_X2 + kq * 264);
    const ull* x2b = (const ull*)(sm + OFF_X2 + kq * 264 + 132);

    const float* gxp0 = g_gx + ((size_t)bi * S_ * GH + hj) * 256 + kq * 64 + cl;
    float* phs = g_hs + (size_t)(bg0 + kq) * S_ * H_ + hg0 + hl;

    float st_c = 0.f, st_cn = 0.f, st_o = 0.f;
    const int inG0 = (kq < 2);

    if (tid == 0) {
#pragma unroll
        for (int i2 = 0; i2 < 8; i2++) MB_INIT(mbar0 + i2 * 8, 1);
        EXPECT_TX(mbar0 + 0,  2048); EXPECT_TX(mbar0 + 8,  2048);  // A0
        EXPECT_TX(mbar0 + 16, 2048); EXPECT_TX(mbar0 + 24, 2048);  // A1
        EXPECT_TX(mbar0 + 32, 1024); EXPECT_TX(mbar0 + 40, 1024);  // B0
        EXPECT_TX(mbar0 + 48, 1024); EXPECT_TX(mbar0 + 56, 1024);  // B1
    }
    __syncthreads();
    cluster_sync();    // weights + zero staging + primed barriers cluster-wide

    float gxv = __ldcg(gxp0);

    // ---------------- recurrence (no __syncthreads in loop) ----------------
    for (int t = 0; t < S_; t++) {
        const int pb = t & 1;
        const uint32_t wpar = (uint32_t)((t >> 1) & 1);
        const uint32_t mA0 = mbar0 + 0  + pb * 8;
        const uint32_t mA1 = mbar0 + 16 + pb * 8;
        const uint32_t mB0 = mbar0 + 32 + pb * 8;
        const uint32_t mB1 = mbar0 + 48 + pb * 8;

        // ======== phase 1: mv1 G0 + act1 G0 ========
        {
            ull acc0 = 0, acc1 = 0;
#pragma unroll
            for (int j = 0; j < 8; j++) {
                float4 wv4 = w4a[j * 64];
                ull wp;
                PACK2(wp, wv4.x, wv4.x); FMA2(acc0, wp, x1[(j * 4 + 0) * 2], acc0);
                PACK2(wp, wv4.y, wv4.y); FMA2(acc1, wp, x1[(j * 4 + 1) * 2], acc1);
                PACK2(wp, wv4.z, wv4.z); FMA2(acc0, wp, x1[(j * 4 + 2) * 2], acc0);
                PACK2(wp, wv4.w, wv4.w); FMA2(acc1, wp, x1[(j * 4 + 3) * 2], acc1);
            }
            asm("add.rn.f32x2 %0, %0, %1;" : "+l"(acc0) : "l"(acc1));
            float s0, s1; UNPACK2(s0, s1, acc0);
            s0 += __shfl_xor_sync(~0u, s0, 8);  s1 += __shfl_xor_sync(~0u, s1, 8);
            s0 += __shfl_xor_sync(~0u, s0, 16); s1 += __shfl_xor_sync(~0u, s1, 16);
            float sv = (kq & 1) ? s1 : s0;
            float y = fmaf(actA, tanhapx(actS * (sv + gxv)), actC);
            float p  = __shfl_xor_sync(~0u, y, 1);
            float qv = __shfl_xor_sync(~0u, y, 2);
            float r2 = __shfl_xor_sync(~0u, p, 2);
            float gi = (g == 0) ? y : (g == 1) ? p : (g == 2) ? qv : r2;
            float gf = (g == 1) ? y : (g == 0) ? p : (g == 3) ? qv : r2;
            float go = (g == 2) ? y : (g == 3) ? p : (g == 0) ? qv : r2;
            float gg = (g == 3) ? y : (g == 2) ? p : (g == 1) ? qv : r2;
            if (inG0) {
                st_o = go;
                if (g < 2) {
                    float v = (g == 0) ? (gi * gg) : (gf * st_c);
#pragma unroll
                    for (int r = 0; r < GH; r++)
                        st_async_b32(mapa_rank(aA, r), v, mapa_rank(mA0, r));
                }
            }
        }

        // B1(t-1) must complete before mv1 G1 reads sX1 G1
        if (t > 0) {
            uint32_t mw = mbar0 + 48 + ((t - 1) & 1) * 8;
            waitp(mw, (uint32_t)(((t - 1) >> 1) & 1));
            if (tid == 0) EXPECT_TX(mw, 1024);
        }
        float gx_nxt = __ldcg(gxp0 + (size_t)((t + 1 < S_) ? t + 1 : t) * 2048);

        // ======== phase 2: mv1 G1 + act1 G1 ========
        {
            ull acc0 = 0, acc1 = 0;
#pragma unroll
            for (int j = 0; j < 8; j++) {
                float4 wv4 = w4a[j * 64];
                ull wp;
                PACK2(wp, wv4.x, wv4.x); FMA2(acc0, wp, x1[(j * 4 + 0) * 2 + 1], acc0);
                PACK2(wp, wv4.y, wv4.y); FMA2(acc1, wp, x1[(j * 4 + 1) * 2 + 1], acc1);
                PACK2(wp, wv4.z, wv4.z); FMA2(acc0, wp, x1[(j * 4 + 2) * 2 + 1], acc0);
                PACK2(wp, wv4.w, wv4.w); FMA2(acc1, wp, x1[(j * 4 + 3) * 2 + 1], acc1);
            }
            asm("add.rn.f32x2 %0, %0, %1;" : "+l"(acc0) : "l"(acc1));
            float s0, s1; UNPACK2(s0, s1, acc0);
            s0 += __shfl_xor_sync(~0u, s0, 8);  s1 += __shfl_xor_sync(~0u, s1, 8);
            s0 += __shfl_xor_sync(~0u, s0, 16); s1 += __shfl_xor_sync(~0u, s1, 16);
            float sv = (kq & 1) ? s1 : s0;
            float y = fmaf(actA, tanhapx(actS * (sv + gxv)), actC);
            float p  = __shfl_xor_sync(~0u, y, 1);
            float qv = __shfl_xor_sync(~0u, y, 2);
            float r2 = __shfl_xor_sync(~0u, p, 2);
            float gi = (g == 0) ? y : (g == 1) ? p : (g == 2) ? qv : r2;
            float gf = (g == 1) ? y : (g == 0) ? p : (g == 3) ? qv : r2;
            float go = (g == 2) ? y : (g == 3) ? p : (g == 0) ? qv : r2;
            float gg = (g == 3) ? y : (g == 2) ? p : (g == 1) ? qv : r2;
            if (!inG0) {
                st_o = go;
                if (g < 2) {
                    float v = (g == 0) ? (gi * gg) : (gf * st_c);
#pragma unroll
                    for (int r = 0; r < GH; r++)
                        st_async_b32(mapa_rank(aA, r), v, mapa_rank(mA1, r));
                }
            }
        }

        waitp(mA0, wpar);
        if (tid == 0) EXPECT_TX(mA0, 2048);

        // ======== phase 3: mv2 G0 + act2 G0 ========
        {
            ull acc0 = 0, acc1 = 0;
#pragma unroll
            for (int j = 0; j < 8; j++) {
                float4 wv4 = w4b[j * 64];
                ull wp;
                PACK2(wp, wv4.x, wv4.x); FMA2(acc0, wp, x2a[(j * 4 + 0) * 2], acc0);
                PACK2(wp, wv4.y, wv4.y); FMA2(acc1, wp, x2a[(j * 4 + 1) * 2], acc1);
                PACK2(wp, wv4.z, wv4.z); FMA2(acc0, wp, x2a[(j * 4 + 2) * 2], acc0);
                PACK2(wp, wv4.w, wv4.w); FMA2(acc1, wp, x2a[(j * 4 + 3) * 2], acc1);
            }
#pragma unroll
            for (int j = 8; j < 16; j++) {
                float4 wv4 = w4b[j * 64];
                ull wp;
                PACK2(wp, wv4.x, wv4.x); FMA2(acc0, wp, x2b[((j - 8) * 4 + 0) * 2], acc0);
                PACK2(wp, wv4.y, wv4.y); FMA2(acc1, wp, x2b[((j - 8) * 4 + 1) * 2], acc1);
                PACK2(wp, wv4.z, wv4.z); FMA2(acc0, wp, x2b[((j - 8) * 4 + 2) * 2], acc0);
                PACK2(wp, wv4.w, wv4.w); FMA2(acc1, wp, x2b[((j - 8) * 4 + 3) * 2], acc1);
            }
            asm("add.rn.f32x2 %0, %0, %1;" : "+l"(acc0) : "l"(acc1));
            float s0, s1; UNPACK2(s0, s1, acc0);
            s0 += __shfl_xor_sync(~0u, s0, 8);  s1 += __shfl_xor_sync(~0u, s1, 8);
            s0 += __shfl_xor_sync(~0u, s0, 16); s1 += __shfl_xor_sync(~0u, s1, 16);
            float sv = (kq & 1) ? s1 : s0;
            float y = fmaf(actA, tanhapx(actS * (sv + b2)), actC);
            float p  = __shfl_xor_sync(~0u, y, 1);
            float qv = __shfl_xor_sync(~0u, y, 2);
            float r2 = __shfl_xor_sync(~0u, p, 2);
            float gi = (g == 0) ? y : (g == 1) ? p : (g == 2) ? qv : r2;
            float gf = (g == 1) ? y : (g == 0) ? p : (g == 3) ? qv : r2;
            float go = (g == 2) ? y : (g == 3) ? p : (g == 0) ? qv : r2;
            float gg = (g == 3) ? y : (g == 2) ? p : (g == 1) ? qv : r2;
            if (inG0) {
                st_cn = fmaf(gf, st_cn, gi * gg);
                float cv = go * tanhapx(st_cn);
                st_c = cv;
                float hv = st_o * tanhapx(cv);
                if (g == 2) {
#pragma unroll
                    for (int r = 0; r < GH; r++)
                        st_async_b32(mapa_rank(aB, r), hv, mapa_rank(mB0, r));
                } else if (g == 3) {
                    __stcg(phs, hv);
                }
            }
        }

        waitp(mA1, wpar);
        if (tid == 0) EXPECT_TX(mA1, 2048);

        // ======== phase 4: mv2 G1 + act2 G1 ========
        {
            ull acc0 = 0, acc1 = 0;
#pragma unroll
            for (int j = 0; j < 8; j++) {
                float4 wv4 = w4b[j * 64];
                ull wp;
                PACK2(wp, wv4.x, wv4.x); FMA2(acc0, wp, x2a[(j * 4 + 0) * 2 + 1], acc0);
                PACK2(wp, wv4.y, wv4.y); FMA2(acc1, wp, x2a[(j * 4 + 1) * 2 + 1], acc1);
                PACK2(wp, wv4.z, wv4.z); FMA2(acc0, wp, x2a[(j * 4 + 2) * 2 + 1], acc0);
                PACK2(wp, wv4.w, wv4.w); FMA2(acc1, wp, x2a[(j * 4 + 3) * 2 + 1], acc1);
            }
#pragma unroll
            for (int j = 8; j < 16; j++) {
                float4 wv4 = w4b[j * 64];
                ull wp;
                PACK2(wp, wv4.x, wv4.x); FMA2(acc0, wp, x2b[((j - 8) * 4 + 0) * 2 + 1], acc0);
                PACK2(wp, wv4.y, wv4.y); FMA2(acc1, wp, x2b[((j - 8) * 4 + 1) * 2 + 1], acc1);
                PACK2(wp, wv4.z, wv4.z); FMA2(acc0, wp, x2b[((j - 8) * 4 + 2) * 2 + 1], acc0);
                PACK2(wp, wv4.w, wv4.w); FMA2(acc1, wp, x2b[((j - 8) * 4 + 3) * 2 + 1], acc1);
            }
            asm("add.rn.f32x2 %0, %0, %1;" : "+l"(acc0) : "l"(acc1));
            float s0, s1; UNPACK2(s0, s1, acc0);
            s0 += __shfl_xor_sync(~0u, s0, 8);  s1 += __shfl_xor_sync(~0u, s1, 8);
            s0 += __shfl_xor_sync(~0u, s0, 16); s1 += __shfl_xor_sync(~0u, s1, 16);
            float sv = (kq & 1) ? s1 : s0;
            float y = fmaf(actA, tanhapx(actS * (sv + b2)), actC);
            float p  = __shfl_xor_sync(~0u, y, 1);
            float qv = __shfl_xor_sync(~0u, y, 2);
            float r2 = __shfl_xor_sync(~0u, p, 2);
            float gi = (g == 0) ? y : (g == 1) ? p : (g == 2) ? qv : r2;
            float gf = (g == 1) ? y : (g == 0) ? p : (g == 3) ? qv : r2;
            float go = (g == 2) ? y : (g == 3) ? p : (g == 0) ? qv : r2;
            float gg = (g == 3) ? y : (g == 2) ? p : (g == 1) ? qv : r2;
            if (!inG0) {
                st_cn = fmaf(gf, st_cn, gi * gg);
                float cv = go * tanhapx(st_cn);
                st_c = cv;
                float hv = st_o * tanhapx(cv);
                if (g == 2) {
#pragma unroll
                    for (int r = 0; r < GH; r++)
                        st_async_b32(mapa_rank(aB, r), hv, mapa_rank(mB1, r));
                } else if (g == 3) {
                    __stcg(phs, hv);
                }
            }
        }

        waitp(mB0, wpar);
        if (tid == 0) EXPECT_TX(mB0, 1024);

        gxv = gx_nxt;
        phs += H_;
    }
    cluster_sync();   // all g_hs complete; no CTA exits with peers' st.async pending

    // ---------------- projection: out = hs @ W_lin^T + b_lin ----------------
    {
        float* sWt   = sm;                  // [128 k][64 o]
        float* sTile = sm + 8192;           // [64 r][132]
        float* sBL   = sm + 8192 + 8448;
        for (int idx = tid; idx < H_ * O_; idx += THREADS) {
            int o = idx & 63, k = idx >> 6;
            sWt[k * 64 + o] = W_lin[o * H_ + k];
        }
        if (tid < O_) sBL[tid] = b_lin[tid];
        __syncthreads();

        const int t0 = hj * 256, row = tid >> 2, cg = tid & 3;
        for (int it = 0; it < 16; it++) {
            int b = it >> 2, tr0 = t0 + (it & 3) * 64;
            const float* src = g_hs + ((size_t)(bg0 + b) * S_ + tr0) * H_;
            for (int idx = tid; idx < 64 * H_; idx += THREADS) {
                int r = idx >> 7, k = idx & 127;
                sTile[r * 132 + k] = src[idx];
            }
            __syncthreads();

            float accp[16];
#pragma unroll
            for (int j = 0; j < 16; j++) accp[j] = sBL[cg * 16 + j];
            const float* hrow = sTile + row * 132;
#pragma unroll 4
            for (int k4 = 0; k4 < 32; k4++) {
                float4 hx = *(const float4*)(hrow + k4 * 4);
#pragma unroll
                for (int kk = 0; kk < 4; kk++) {
                    float hv = (kk == 0) ? hx.x : (kk == 1) ? hx.y : (kk == 2) ? hx.z : hx.w;
                    const float* wr = sWt + (k4 * 4 + kk) * 64 + cg * 16;
#pragma unroll
                    for (int j = 0; j < 16; j++)
                        accp[j] = fmaf(hv, wr[j], accp[j]);
                }
            }
            float* orow = out + ((size_t)(bg0 + b) * S_ + tr0 + row) * O_ + cg * 16;
#pragma unroll
            for (int j = 0; j < 16; j += 4)
                *(float4*)(orow + j) = make_float4(accp[j], accp[j+1], accp[j+2], accp[j+3]);
            __syncthreads();
        }
    }
}

// ---------------- launch ----------------
extern "C" void kernel_launch(void* const* d_in, const int* in_sizes, int n_in,
                              void* d_out, int out_size)
{
    const float* x      = (const float*)d_in[0];
    const float* Wx_out = (const float*)d_in[1];
    const float* Wh_out = (const float*)d_in[2];
    const float* b_out  = (const float*)d_in[3];
    const float* Wx_in  = (const float*)d_in[4];
    const float* Wh_in  = (const float*)d_in[5];
    const float* b_in   = (const float*)d_in[6];
    const float* W_lin  = (const float*)d_in[7];
    const float* b_lin  = (const float*)d_in[8];
    float* out = (float*)d_out;

    prepass<<<dim3(8, GH, NC), 256>>>(x, Wx_out, b_out);

    (void)cudaFuncSetAttribute(nlstm_rec,
                               cudaFuncAttributeMaxDynamicSharedMemorySize, SMEM_BYTES);
    nlstm_rec<<<dim3(GH, NC), THREADS, SMEM_BYTES>>>(
        Wh_out, Wx_in, Wh_in, b_in, W_lin, b_lin, out);
}

// round 17
// speedup vs baseline: 1.4017x; 1.4017x over previous
#include <cuda_runtime.h>
#include <cstdint>

#define B_ 128
#define I_ 64
#define S_ 2048
#define H_ 128
#define O_ 64
#define G4H 512
#define NC 32          // clusters (batch groups)
#define GH 4           // CTAs per cluster (h-slices, 32 h each)
#define BPC 4          // batches per cluster
#define THREADS 512

typedef unsigned long long ull;

// ---------------- device scratch (static) ----------------
__device__ float g_gx[(size_t)NC * S_ * 512 * 4];   // [bi][t][gcol 512][b 4]
__device__ float g_hs[(size_t)B_ * S_ * H_];        // [b][t][h]

// ---------------- smem layout (float offsets) ----------------
// W1: float4 idx = kq*1025 + j*128 + cl   (4 sections, j<8,  cl<128)
// W2: float4 idx = kq*2049 + j*128 + cl   (4 sections, j<16, cl<128)
// sX1: k<128 : f = (k>>5)*132 + (k&31)*4 + b
// sX2: k<256 : f = (k>>5)*132 + (k&31)*4 + b
#define OFF_W1 0
#define OFF_W2 16400
#define OFF_X1 49184
#define OFF_X2 49712
#define MBAR_F 50768               // 4 mbarriers x 8B (A0,A1,B0,B1)
#define SMEM_FLOATS 50776
#define SMEM_BYTES (SMEM_FLOATS * 4)   // 203104 B -> 1 CTA/SM

#define FMA2(d,a,b,c)  asm("fma.rn.f32x2 %0, %1, %2, %3;" : "=l"(d) : "l"(a), "l"(b), "l"(c))
#define PACK2(d,lo,hi) asm("mov.b64 %0, {%1, %2};" : "=l"(d) : "f"(lo), "f"(hi))
#define UNPACK2(lo,hi,s) asm("mov.b64 {%0, %1}, %2;" : "=f"(lo), "=f"(hi) : "l"(s))

__device__ __forceinline__ float tanhapx(float x) {
    float y; asm("tanh.approx.f32 %0, %1;" : "=f"(y) : "f"(x)); return y;
}
__device__ __forceinline__ uint32_t smem_u32(const void* p) {
    uint32_t a;
    asm("{ .reg .u64 t; cvta.to.shared.u64 t, %1; cvt.u32.u64 %0, t; }" : "=r"(a) : "l"(p));
    return a;
}
__device__ __forceinline__ uint32_t mapa_rank(uint32_t laddr, uint32_t rank) {
    uint32_t ra;
    asm("mapa.shared::cluster.u32 %0, %1, %2;" : "=r"(ra) : "r"(laddr), "r"(rank));
    return ra;
}
__device__ __forceinline__ void st_async_b32(uint32_t da, float v, uint32_t ma) {
    asm volatile("st.async.shared::cluster.mbarrier::complete_tx::bytes.b32 [%0], %1, [%2];"
                 :: "r"(da), "r"(__float_as_uint(v)), "r"(ma) : "memory");
}
#define MB_INIT(mb, n) asm volatile("mbarrier.init.shared.b64 [%0], %1;" :: "r"(mb), "r"((uint32_t)(n)) : "memory")
#define EXPECT_TX(mb, n) asm volatile("mbarrier.arrive.expect_tx.shared.b64 _, [%0], %1;" :: "r"(mb), "r"((uint32_t)(n)) : "memory")
__device__ __forceinline__ void waitp(uint32_t mb, uint32_t par) {
    uint32_t done;
    do {
        asm volatile("{\n\t.reg .pred p;\n\t"
            "mbarrier.try_wait.parity.acquire.cta.shared::cta.b64 p, [%1], %2, 0x989680;\n\t"
            "selp.b32 %0, 1, 0, p;\n\t}"
            : "=r"(done) : "r"(mb), "r"(par) : "memory");
    } while (!done);
}
__device__ __forceinline__ void cluster_sync() {
    asm volatile("barrier.cluster.arrive.aligned;\n\t"
                 "barrier.cluster.wait.aligned;" ::: "memory");
}

// ================= pre-pass: gx = x_t @ Wx_out + b_out =================
// grid (8 tchunks, 8 h-slices, NC), 256 threads. Writes g_gx[bi][t][gcol][b].
__global__ __launch_bounds__(256) void prepass(const float* __restrict__ x,
                                               const float* __restrict__ Wx_out,
                                               const float* __restrict__ b_out)
{
    __shared__ float sW[64 * 64];       // [i][cl]
    __shared__ float sx[4 * 64 * 16];   // [b][i][16t]
    const int tid = threadIdx.x;
    const int tc = blockIdx.x, hjp = blockIdx.y, bi = blockIdx.z;
    const int cl = tid & 63, b = tid >> 6;
    const int gcl = (cl & 3) * H_ + hjp * 16 + (cl >> 2);   // canonical g*128+h

    for (int idx = tid; idx < 64 * 64; idx += 256) {
        int i = idx >> 6, c2 = idx & 63;
        int gc2 = (c2 & 3) * H_ + hjp * 16 + (c2 >> 2);
        sW[idx] = Wx_out[i * G4H + gc2];
    }
    const float bias = b_out[gcl];
    __syncthreads();

    for (int tile = 0; tile < 16; tile++) {
        int t0 = tc * 256 + tile * 16;
        for (int n = 0; n < 16; n++) {
            int flat = n * 256 + tid;
            int ttl = flat & 15, i = (flat >> 4) & 63, bb = flat >> 10;
            sx[(bb * 64 + i) * 16 + ttl] =
                x[((size_t)(bi * 4 + bb) * 64 + i) * S_ + t0 + ttl];
        }
        __syncthreads();

        ull acc[8];
#pragma unroll
        for (int tp = 0; tp < 8; tp++) PACK2(acc[tp], bias, bias);
#pragma unroll 8
        for (int i = 0; i < 64; i++) {
            float wv = sW[i * 64 + cl];
            ull wp; PACK2(wp, wv, wv);
            const ull* xp = (const ull*)(sx + (b * 64 + i) * 16);
#pragma unroll
            for (int tp = 0; tp < 8; tp++) FMA2(acc[tp], wp, xp[tp], acc[tp]);
        }
        float* outp = g_gx + ((size_t)bi * S_ + t0) * 2048 + gcl * 4 + b;
#pragma unroll
        for (int tp = 0; tp < 8; tp++) {
            float lo, hi; UNPACK2(lo, hi, acc[tp]);
            outp[(size_t)(2 * tp) * 2048]     = lo;
            outp[(size_t)(2 * tp + 1) * 2048] = hi;
        }
        __syncthreads();
    }
}

// ================= main recurrent kernel =================
__global__ void __cluster_dims__(GH, 1, 1) __launch_bounds__(THREADS, 1)
nlstm_rec(const float* __restrict__ Wh_out,
          const float* __restrict__ Wx_in, const float* __restrict__ Wh_in,
          const float* __restrict__ b_in,
          const float* __restrict__ W_lin, const float* __restrict__ b_lin,
          float* __restrict__ out)
{
    extern __shared__ float sm[];
    const int tid = threadIdx.x;
    const int hj = blockIdx.x;          // 0..3
    const int bi = blockIdx.y;          // 0..31
    const int bg0 = bi * BPC;
    const int hg0 = hj * 32;
    const uint32_t sbase = smem_u32(sm);
    const uint32_t mbar0 = sbase + MBAR_F * 4;   // A0,A1,B0,B1 at +0,+8,+16,+24

    // ---- load weight slices into padded SMEM ----
    for (int idx = tid; idx < 128 * 128; idx += THREADS) {
        int k = idx >> 7, cl2 = idx & 127;
        int gc = (cl2 & 3) * H_ + hg0 + (cl2 >> 2);
        int k4 = k >> 2, e = k & 3, kqq = k4 >> 3, j = k4 & 7;
        sm[OFF_W1 + (kqq * 1025 + j * 128 + cl2) * 4 + e] = Wh_out[k * G4H + gc];
    }
    for (int idx = tid; idx < 256 * 128; idx += THREADS) {
        int k = idx >> 7, cl2 = idx & 127;
        int gc = (cl2 & 3) * H_ + hg0 + (cl2 >> 2);
        int k4 = k >> 2, e = k & 3, kqq = k4 >> 4, j = k4 & 15;
        sm[OFF_W2 + (kqq * 2049 + j * 128 + cl2) * 4 + e] =
            (k < H_) ? Wx_in[k * G4H + gc] : Wh_in[(k - H_) * G4H + gc];
    }
    // zero staging (h(0) = 0; pads unread)
    for (int idx = tid; idx < 528 + 1056; idx += THREADS)
        sm[OFF_X1 + idx] = 0.0f;

    // ---- roles ----
    const int warp = tid >> 5, lane = tid & 31;
    const int cl = warp * 8 + (lane & 7);   // gate column 0..127 (= hl*4+g)
    const int kq = lane >> 3;               // k-quarter AND own batch (0..3)
    const int g  = cl & 3;
    const int hl = cl >> 2;                 // 0..31
    const int hh = hg0 + hl;
    const int gcol = g * H_ + hh;

    const float b2 = b_in[gcol];
    const float actA = (g == 3) ? 1.f : 0.5f;
    const float actS = (g == 3) ? 1.f : 0.5f;
    const float actC = (g == 3) ? 0.f : 0.5f;

    // exchange data addresses (hoisted mapa per rank)
    const int kA = (g == 0) ? hh : (H_ + hh);
    const uint32_t aA = sbase + (uint32_t)(OFF_X2 + (kA >> 5) * 132 + (kA & 31) * 4 + kq) * 4;
    const uint32_t aB = sbase + (uint32_t)(OFF_X1 + (hh >> 5) * 132 + (hh & 31) * 4 + kq) * 4;
    uint32_t dA[GH], dB[GH];
#pragma unroll
    for (int r = 0; r < GH; r++) { dA[r] = mapa_rank(aA, r); dB[r] = mapa_rank(aB, r); }

    // matvec pointers
    const float4* w4a = (const float4*)(sm + OFF_W1) + kq * 1025 + cl;
    const float4* w4b = (const float4*)(sm + OFF_W2) + kq * 2049 + cl;
    const ulonglong2* x1  = (const ulonglong2*)(sm + OFF_X1 + kq * 132);
    const ulonglong2* x2a = (const ulonglong2*)(sm + OFF_X2 + (2 * kq) * 132);
    const ulonglong2* x2b = (const ulonglong2*)(sm + OFF_X2 + (2 * kq + 1) * 132);

    const float* gxp0 = g_gx + (size_t)bi * S_ * 2048 + gcol * 4 + kq;
    float* phs = g_hs + (size_t)(bg0 + kq) * S_ * H_ + hh;

    float st_c = 0.f, st_cn = 0.f, st_o = 0.f;

    if (tid == 0) {
        MB_INIT(mbar0 + 0, 1);  MB_INIT(mbar0 + 8, 1);
        MB_INIT(mbar0 + 16, 1); MB_INIT(mbar0 + 24, 1);
        EXPECT_TX(mbar0 + 0, 4096);  EXPECT_TX(mbar0 + 8, 4096);   // A0, A1
        EXPECT_TX(mbar0 + 16, 2048); EXPECT_TX(mbar0 + 24, 2048);  // B0, B1
    }
    __syncthreads();
    cluster_sync();    // weights + zeroed staging + primed barriers cluster-wide

    float gxv = __ldcg(gxp0);

    // ---------------- recurrence (no __syncthreads, no barrier.cluster) ----------------
    for (int t = 0; t < S_; t++) {
        const int pb = t & 1;
        const uint32_t wpar = (uint32_t)((t >> 1) & 1);
        const uint32_t mA = mbar0 + pb * 8;
        const uint32_t mB = mbar0 + 16 + pb * 8;

        // ---- mv1: h(t-1) @ Wh_out (k = kq*32..+32) ----
        ull acc0 = 0, acc1 = 0;
#pragma unroll
        for (int j = 0; j < 8; j++) {
            float4 wv4 = w4a[j * 128];
            ull wp; ulonglong2 xv;
            PACK2(wp, wv4.x, wv4.x); xv = x1[j * 4 + 0]; FMA2(acc0, wp, xv.x, acc0); FMA2(acc1, wp, xv.y, acc1);
            PACK2(wp, wv4.y, wv4.y); xv = x1[j * 4 + 1]; FMA2(acc0, wp, xv.x, acc0); FMA2(acc1, wp, xv.y, acc1);
            PACK2(wp, wv4.z, wv4.z); xv = x1[j * 4 + 2]; FMA2(acc0, wp, xv.x, acc0); FMA2(acc1, wp, xv.y, acc1);
            PACK2(wp, wv4.w, wv4.w); xv = x1[j * 4 + 3]; FMA2(acc0, wp, xv.x, acc0); FMA2(acc1, wp, xv.y, acc1);
        }
        // ---- k-reduce (xor 8,16) + act1 ----
        {
            float s0, s1, s2, s3;
            UNPACK2(s0, s1, acc0); UNPACK2(s2, s3, acc1);
            s0 += __shfl_xor_sync(~0u, s0, 8);  s1 += __shfl_xor_sync(~0u, s1, 8);
            s2 += __shfl_xor_sync(~0u, s2, 8);  s3 += __shfl_xor_sync(~0u, s3, 8);
            s0 += __shfl_xor_sync(~0u, s0, 16); s1 += __shfl_xor_sync(~0u, s1, 16);
            s2 += __shfl_xor_sync(~0u, s2, 16); s3 += __shfl_xor_sync(~0u, s3, 16);
            float u0 = (kq & 1) ? s1 : s0, u1 = (kq & 1) ? s3 : s2;
            float sv = (kq & 2) ? u1 : u0;
            float y = fmaf(actA, tanhapx(actS * (sv + gxv)), actC);
            float p  = __shfl_xor_sync(~0u, y, 1);
            float qv = __shfl_xor_sync(~0u, y, 2);
            float r2 = __shfl_xor_sync(~0u, p, 2);
            float gi = (g == 0) ? y : (g == 1) ? p : (g == 2) ? qv : r2;
            float gf = (g == 1) ? y : (g == 0) ? p : (g == 3) ? qv : r2;
            float go = (g == 2) ? y : (g == 3) ? p : (g == 0) ? qv : r2;
            float gg = (g == 3) ? y : (g == 2) ? p : (g == 1) ? qv : r2;
            st_o = go;
            if (g < 2) {
                float v = (g == 0) ? (gi * gg) : (gf * st_c);
#pragma unroll
                for (int r = 0; r < GH; r++)
                    st_async_b32(dA[r], v, mapa_rank(mA, r));
            }
        }

        float gx_nxt = __ldcg(gxp0 + (size_t)((t + 1 < S_) ? t + 1 : t) * 2048);

        waitp(mA, wpar);
        if (tid == 0) EXPECT_TX(mA, 4096);

        // ---- mv2: [x_in|h_in] @ W_in (k = kq*64..+64) ----
        acc0 = 0; acc1 = 0;
#pragma unroll
        for (int j = 0; j < 16; j++) {
            float4 wv4 = w4b[j * 128];
            const ulonglong2* xs = (j < 8) ? x2a : x2b;
            int jj = (j < 8) ? j : (j - 8);
            ull wp; ulonglong2 xv;
            PACK2(wp, wv4.x, wv4.x); xv = xs[jj * 4 + 0]; FMA2(acc0, wp, xv.x, acc0); FMA2(acc1, wp, xv.y, acc1);
            PACK2(wp, wv4.y, wv4.y); xv = xs[jj * 4 + 1]; FMA2(acc0, wp, xv.x, acc0); FMA2(acc1, wp, xv.y, acc1);
            PACK2(wp, wv4.z, wv4.z); xv = xs[jj * 4 + 2]; FMA2(acc0, wp, xv.x, acc0); FMA2(acc1, wp, xv.y, acc1);
            PACK2(wp, wv4.w, wv4.w); xv = xs[jj * 4 + 3]; FMA2(acc0, wp, xv.x, acc0); FMA2(acc1, wp, xv.y, acc1);
        }
        // ---- k-reduce + act2 ----
        {
            float s0, s1, s2, s3;
            UNPACK2(s0, s1, acc0); UNPACK2(s2, s3, acc1);
            s0 += __shfl_xor_sync(~0u, s0, 8);  s1 += __shfl_xor_sync(~0u, s1, 8);
            s2 += __shfl_xor_sync(~0u, s2, 8);  s3 += __shfl_xor_sync(~0u, s3, 8);
            s0 += __shfl_xor_sync(~0u, s0, 16); s1 += __shfl_xor_sync(~0u, s1, 16);
            s2 += __shfl_xor_sync(~0u, s2, 16); s3 += __shfl_xor_sync(~0u, s3, 16);
            float u0 = (kq & 1) ? s1 : s0, u1 = (kq & 1) ? s3 : s2;
            float sv = (kq & 2) ? u1 : u0;
            float y = fmaf(actA, tanhapx(actS * (sv + b2)), actC);
            float p  = __shfl_xor_sync(~0u, y, 1);
            float qv = __shfl_xor_sync(~0u, y, 2);
            float r2 = __shfl_xor_sync(~0u, p, 2);
            float gi = (g == 0) ? y : (g == 1) ? p : (g == 2) ? qv : r2;
            float gf = (g == 1) ? y : (g == 0) ? p : (g == 3) ? qv : r2;
            float go = (g == 2) ? y : (g == 3) ? p : (g == 0) ? qv : r2;
            float gg = (g == 3) ? y : (g == 2) ? p : (g == 1) ? qv : r2;
            st_cn = fmaf(gf, st_cn, gi * gg);
            float cv = go * tanhapx(st_cn);
            st_c = cv;
            float hv = st_o * tanhapx(cv);
            if (g == 2) {
#pragma unroll
                for (int r = 0; r < GH; r++)
                    st_async_b32(dB[r], hv, mapa_rank(mB, r));
            } else if (g == 3) {
                __stcg(phs, hv);
            }
        }
        phs += H_;

        waitp(mB, wpar);
        if (tid == 0) EXPECT_TX(mB, 2048);

        gxv = gx_nxt;
    }
    cluster_sync();   // no CTA exits/overwrites SMEM while peers' st.async pending

    // ---------------- projection: out = hs @ W_lin^T + b_lin ----------------
    {
        float* sWt   = sm;                  // [128 k][64 o] = 8192 f
        float* sTile = sm + 8192;           // [64 r][132]   = 8448 f
        float* sBL   = sm + 8192 + 8448;    // 64 f
        for (int idx = tid; idx < H_ * O_; idx += THREADS) {
            int o = idx & 63, k = idx >> 6;
            sWt[k * 64 + o] = W_lin[o * H_ + k];
        }
        if (tid < O_) sBL[tid] = b_lin[tid];
        __syncthreads();

        const int t0 = hj * 512, row = tid >> 3, cg = tid & 7;
        for (int it = 0; it < 32; it++) {
            int b = it >> 3, tr0 = t0 + (it & 7) * 64;
            const float* src = g_hs + ((size_t)(bg0 + b) * S_ + tr0) * H_;
            for (int idx = tid; idx < 64 * H_; idx += THREADS) {
                int r = idx >> 7, k = idx & 127;
                sTile[r * 132 + k] = src[idx];
            }
            __syncthreads();

            float accp[8];
#pragma unroll
            for (int j = 0; j < 8; j++) accp[j] = sBL[cg * 8 + j];
            const float* hrow = sTile + row * 132;
#pragma unroll 8
            for (int k4 = 0; k4 < 32; k4++) {
                float4 hx = *(const float4*)(hrow + k4 * 4);
#pragma unroll
                for (int kk = 0; kk < 4; kk++) {
                    float hv = (kk == 0) ? hx.x : (kk == 1) ? hx.y : (kk == 2) ? hx.z : hx.w;
                    const float* wr = sWt + (k4 * 4 + kk) * 64 + cg * 8;
                    float4 w0 = *(const float4*)(wr);
                    float4 w1 = *(const float4*)(wr + 4);
                    accp[0] = fmaf(hv, w0.x, accp[0]); accp[1] = fmaf(hv, w0.y, accp[1]);
                    accp[2] = fmaf(hv, w0.z, accp[2]); accp[3] = fmaf(hv, w0.w, accp[3]);
                    accp[4] = fmaf(hv, w1.x, accp[4]); accp[5] = fmaf(hv, w1.y, accp[5]);
                    accp[6] = fmaf(hv, w1.z, accp[6]); accp[7] = fmaf(hv, w1.w, accp[7]);
                }
            }
            float* orow = out + ((size_t)(bg0 + b) * S_ + tr0 + row) * O_ + cg * 8;
            *(float4*)(orow)     = make_float4(accp[0], accp[1], accp[2], accp[3]);
            *(float4*)(orow + 4) = make_float4(accp[4], accp[5], accp[6], accp[7]);
            __syncthreads();
        }
    }
}

// ---------------- launch ----------------
extern "C" void kernel_launch(void* const* d_in, const int* in_sizes, int n_in,
                              void* d_out, int out_size)
{
    const float* x      = (const float*)d_in[0];
    const float* Wx_out = (const float*)d_in[1];
    const float* Wh_out = (const float*)d_in[2];
    const float* b_out  = (const float*)d_in[3];
    const float* Wx_in  = (const float*)d_in[4];
    const float* Wh_in  = (const float*)d_in[5];
    const float* b_in   = (const float*)d_in[6];
    const float* W_lin  = (const float*)d_in[7];
    const float* b_lin  = (const float*)d_in[8];
    float* out = (float*)d_out;

    prepass<<<dim3(8, 8, NC), 256>>>(x, Wx_out, b_out);

    (void)cudaFuncSetAttribute(nlstm_rec,
                               cudaFuncAttributeMaxDynamicSharedMemorySize, SMEM_BYTES);
    nlstm_rec<<<dim3(GH, NC), THREADS, SMEM_BYTES>>>(
        Wh_out, Wx_in, Wh_in, b_in, W_lin, b_lin, out);
}